// round 1
// baseline (speedup 1.0000x reference)
#include <cuda_runtime.h>
#include <cuda_bf16.h>
#include <math.h>

// ---------------------------------------------------------------------------
// Problem constants
// ---------------------------------------------------------------------------
#define G_      16
#define C_      4
#define R_      64
#define MUL_    128
#define KDIM    36          // (LMAX+1)^2
#define RB      180
#define RA      359
#define NPIX    (RB*RA)     // 64620
#define EMB     4608
#define NIRR    768

#define RSQRT_MUL 0.08838834764831845f   // 1/sqrt(128)
#define RSQRT_RAD 0.125f                 // 1/sqrt(64)
#define B0C       0.28209479177387814f   // Y00 = 1/sqrt(4*pi)
#define PI_D      3.14159265358979323846

// output layout: concat of the 4 returned tensors, flattened, in order
#define OFF_LPC  0
#define OFF_POS  147456                          // 16*4*64*36
#define OFF_ANG  (OFF_POS + 66170880)            // + 16*64*64620
#define OFF_RAD  (OFF_ANG + 1033920)             // + 16*64620

// ---------------------------------------------------------------------------
// Device scratch (no allocations allowed)
// ---------------------------------------------------------------------------
__device__ float g_F[RB][KDIM];      // beta-dependent SH factor (incl. norm & sqrt2)
__device__ float g_ang[G_*C_*KDIM];  // angular coefficients
__device__ float g_rad[G_*R_];       // radial logits

__device__ __forceinline__ int lofk(int k) {
    const int t[36] = {0,1,1,1,2,2,2,2,2,3,3,3,3,3,3,3,
                       4,4,4,4,4,4,4,4,4,5,5,5,5,5,5,5,5,5,5,5};
    return t[k];
}

// ---------------------------------------------------------------------------
// K0: Gauss-Legendre nodes (n=180) + normalized associated Legendre -> g_F
// One thread per beta node. Newton: 3 float iters (cheap 4-cyc FFMA chain)
// then 2 double iters -> machine precision.
// ---------------------------------------------------------------------------
__global__ void k_nodes() {
    int b = threadIdx.x;
    if (b >= RB) return;
    const int n = RB;
    int i = n - 1 - b;   // descending guess index -> ascending y (numpy order)

    double x = cos(PI_D * (i + 0.75) / (n + 0.5));

    // float refinement
    float xf = (float)x;
    #pragma unroll 1
    for (int it = 0; it < 3; it++) {
        float p0 = 1.0f, p1 = xf;
        #pragma unroll 1
        for (int k = 2; k <= n; k++) {
            float a = (2.0f * k - 1.0f) / (float)k;
            float bcoef = (k - 1.0f) / (float)k;
            float p2 = a * xf * p1 - bcoef * p0;
            p0 = p1; p1 = p2;
        }
        float dp = n * (xf * p1 - p0) / (xf * xf - 1.0f);
        xf -= p1 / dp;
    }
    x = (double)xf;

    // double polish
    #pragma unroll 1
    for (int it = 0; it < 2; it++) {
        double p0 = 1.0, p1 = x;
        #pragma unroll 1
        for (int k = 2; k <= n; k++) {
            double a = (2.0 * k - 1.0) / (double)k;
            double bcoef = (k - 1.0) / (double)k;
            double p2 = a * x * p1 - bcoef * p0;
            p0 = p1; p1 = p2;
        }
        double dp = n * (x * p1 - p0) / (x * x - 1.0);
        x -= p1 / dp;
    }

    // associated Legendre up to l=5 (Condon-Shortley), double precision
    double y = x;
    double somx2 = sqrt(fmax(1.0 - y * y, 0.0));
    double P[6][6];
    P[0][0] = 1.0;
    for (int m = 1; m <= 5; m++) P[m][m] = -(2.0 * m - 1.0) * somx2 * P[m-1][m-1];
    for (int m = 0; m < 5; m++)  P[m+1][m] = (2.0 * m + 1.0) * y * P[m][m];
    for (int m = 0; m <= 5; m++)
        for (int l = m + 2; l <= 5; l++)
            P[l][m] = ((2.0*l - 1.0) * y * P[l-1][m] - (l + m - 1.0) * P[l-2][m]) / (double)(l - m);

    double fact[11];
    fact[0] = 1.0;
    for (int t = 1; t <= 10; t++) fact[t] = fact[t-1] * t;

    for (int l = 0; l <= 5; l++) {
        for (int m = 0; m <= l; m++) {
            double N = sqrt((2.0*l + 1.0) / (4.0 * PI_D) * fact[l-m] / fact[l+m]);
            if (m == 0) {
                g_F[b][l*l + l] = (float)(N * P[l][0]);
            } else {
                double v = sqrt(2.0) * N * P[l][m];
                g_F[b][l*l + l + m] = (float)v;  // pairs with cos(m*alpha)
                g_F[b][l*l + l - m] = (float)v;  // pairs with sin(m*alpha)
            }
        }
    }
}

// ---------------------------------------------------------------------------
// K1: per-graph front section: gather focus node, species scaling, radial MLP,
// angular projections, log_position_coeffs + radial_logits outputs.
// One block per graph, 128 threads (= MUL).
// ---------------------------------------------------------------------------
__global__ void k_front(const float* __restrict__ emb,
                        const float* __restrict__ spec,
                        const float* __restrict__ Wr,
                        const float* __restrict__ Wm1,
                        const float* __restrict__ Wm2,
                        const float* __restrict__ Wa0, const float* __restrict__ Wa1,
                        const float* __restrict__ Wa2, const float* __restrict__ Wa3,
                        const float* __restrict__ Wa4, const float* __restrict__ Wa5,
                        const int* __restrict__ focus,
                        const int* __restrict__ tspec,
                        float* __restrict__ out) {
    __shared__ float s_sc[KDIM][MUL_ + 1];   // scaled irreps, padded vs bank conflicts
    __shared__ float s_r[64];
    __shared__ float s_h[128];
    __shared__ float s_rad[64];

    int g = blockIdx.x;
    int u = threadIdx.x;

    const float* f  = emb  + (size_t)focus[g] * EMB;
    const float* sp = spec + (size_t)tspec[g] * NIRR;

    #pragma unroll
    for (int l = 0; l <= 5; l++) {
        float s = sp[128*l + u];
        int d = 2*l + 1;
        const float* fb = f + 128*l*l + u*d;
        for (int m = 0; m < d; m++) s_sc[l*l + m][u] = fb[m] * s;
    }
    __syncthreads();

    // r = (scal0 @ W_radial) / sqrt(128)
    if (u < 64) {
        float acc = 0.f;
        #pragma unroll 8
        for (int v = 0; v < 128; v++) acc += s_sc[0][v] * Wr[v*64 + u];
        s_r[u] = acc * RSQRT_MUL;
    }
    __syncthreads();

    // h = softplus((r @ W_mlp1)/sqrt(64))
    {
        float acc = 0.f;
        #pragma unroll 8
        for (int j = 0; j < 64; j++) acc += s_r[j] * Wm1[j*128 + u];
        acc *= RSQRT_RAD;
        s_h[u] = fmaxf(acc, 0.f) + log1pf(expf(-fabsf(acc)));
    }
    __syncthreads();

    // radial_logits = (h @ W_mlp2)/sqrt(128)
    if (u < 64) {
        float acc = 0.f;
        #pragma unroll 8
        for (int v = 0; v < 128; v++) acc += s_h[v] * Wm2[v*64 + u];
        acc *= RSQRT_MUL;
        s_rad[u] = acc;
        g_rad[g*64 + u] = acc;
        out[OFF_RAD + g*64 + u] = acc;
    }
    __syncthreads();

    // angular coefficients ang[c][k] + log_position_coeffs
    const float* Wa[6] = {Wa0, Wa1, Wa2, Wa3, Wa4, Wa5};
    for (int o = u; o < C_*KDIM; o += 128) {
        int k = o >> 2, c = o & 3;
        int l = lofk(k);
        const float* w = Wa[l];
        float acc = 0.f;
        #pragma unroll 8
        for (int v = 0; v < 128; v++) acc += s_sc[k][v] * w[v*4 + c];
        acc *= RSQRT_MUL;
        g_ang[(g*C_ + c)*KDIM + k] = acc;

        float* lp = out + OFF_LPC + ((size_t)(g*C_ + c) * R_) * KDIM + k;
        if (k == 0) {
            #pragma unroll 8
            for (int r = 0; r < 64; r++) lp[r*KDIM] = acc + s_rad[r];
        } else {
            #pragma unroll 8
            for (int r = 0; r < 64; r++) lp[r*KDIM] = acc;
        }
    }
}

// ---------------------------------------------------------------------------
// K2 (fused): SH synthesis on the grid -> angular_logits, then broadcast-add
// radial*B0 -> position_logits. One thread per (beta,alpha) pixel; loops g.
// Write-only heavy traffic (no re-read of angular_logits).
// ---------------------------------------------------------------------------
__global__ void k_grid(float* __restrict__ out) {
    __shared__ float s_ang[G_*C_*KDIM];   // 2304
    __shared__ float s_radB[G_*R_];       // 1024, premultiplied by B0
    __shared__ float s_F[KDIM];

    int b = blockIdx.x;
    int a = blockIdx.y * blockDim.x + threadIdx.x;

    for (int i = threadIdx.x; i < G_*C_*KDIM; i += blockDim.x) s_ang[i] = g_ang[i];
    for (int i = threadIdx.x; i < G_*R_;      i += blockDim.x) s_radB[i] = g_rad[i] * B0C;
    if (threadIdx.x < KDIM) s_F[threadIdx.x] = g_F[b][threadIdx.x];
    __syncthreads();

    if (a >= RA) return;

    float cosm[6], sinm[6];
    float al = (float)((2.0 * PI_D / (double)RA) * (double)a);
    sincosf(al, &sinm[1], &cosm[1]);
    cosm[0] = 1.f; sinm[0] = 0.f;
    float c2 = 2.f * cosm[1];
    #pragma unroll
    for (int m = 2; m <= 5; m++) {
        cosm[m] = c2 * cosm[m-1] - cosm[m-2];
        sinm[m] = c2 * sinm[m-1] - sinm[m-2];
    }

    float Bv[KDIM];
    #pragma unroll
    for (int k = 0; k < KDIM; k++) {
        int l = lofk(k);
        int ms = k - l*l - l;
        float t = (ms == 0) ? 1.f : ((ms > 0) ? cosm[ms] : sinm[-ms]);
        Bv[k] = s_F[k] * t;
    }

    int pix = b * RA + a;
    float* outp = out + OFF_POS;
    float* outa = out + OFF_ANG;

    #pragma unroll 1
    for (int g = 0; g < G_; g++) {
        const float* ag = &s_ang[g * C_ * KDIM];
        float v0 = 0.f, v1 = 0.f, v2 = 0.f, v3 = 0.f;
        #pragma unroll
        for (int k = 0; k < KDIM; k++) {
            float bb = Bv[k];
            v0 += ag[k]          * bb;
            v1 += ag[KDIM + k]   * bb;
            v2 += ag[2*KDIM + k] * bb;
            v3 += ag[3*KDIM + k] * bb;
        }
        float mx = fmaxf(fmaxf(v0, v1), fmaxf(v2, v3));
        float lse = mx + logf(expf(v0-mx) + expf(v1-mx) + expf(v2-mx) + expf(v3-mx));

        outa[(size_t)g * NPIX + pix] = lse;

        // position_logits[g, r, :, :] = lse + radial[g,r]*B0
        const float* rb = &s_radB[g * R_];
        float* pp = outp + (size_t)(g * R_) * NPIX + pix;
        #pragma unroll 8
        for (int r = 0; r < R_; r++) {
            pp[0] = lse + rb[r];
            pp += NPIX;
        }
    }
}

// ---------------------------------------------------------------------------
extern "C" void kernel_launch(void* const* d_in, const int* in_sizes, int n_in,
                              void* d_out, int out_size) {
    const float* emb  = (const float*)d_in[0];
    const float* spec = (const float*)d_in[1];
    const float* Wr   = (const float*)d_in[2];
    const float* Wm1  = (const float*)d_in[3];
    const float* Wm2  = (const float*)d_in[4];
    const float* Wa0  = (const float*)d_in[5];
    const float* Wa1  = (const float*)d_in[6];
    const float* Wa2  = (const float*)d_in[7];
    const float* Wa3  = (const float*)d_in[8];
    const float* Wa4  = (const float*)d_in[9];
    const float* Wa5  = (const float*)d_in[10];
    const int* focus  = (const int*)d_in[11];
    const int* tspec  = (const int*)d_in[12];
    float* out = (float*)d_out;

    k_nodes<<<1, 192>>>();
    k_front<<<G_, 128>>>(emb, spec, Wr, Wm1, Wm2,
                         Wa0, Wa1, Wa2, Wa3, Wa4, Wa5,
                         focus, tspec, out);
    dim3 gg(RB, (RA + 127) / 128);
    k_grid<<<gg, 128>>>(out);
}

// round 2
// speedup vs baseline: 3.4726x; 3.4726x over previous
#include <cuda_runtime.h>
#include <cuda_bf16.h>
#include <math.h>

// ---------------------------------------------------------------------------
// Problem constants
// ---------------------------------------------------------------------------
#define G_      16
#define C_      4
#define R_      64
#define MUL_    128
#define KDIM    36          // (LMAX+1)^2
#define RB      180
#define RA      359
#define NPIX    (RB*RA)     // 64620
#define NPIX4   (NPIX/4)    // 16155
#define EMB     4608
#define NIRR    768

#define RSQRT_MUL 0.08838834764831845f   // 1/sqrt(128)
#define RSQRT_RAD 0.125f                 // 1/sqrt(64)
#define B0C       0.28209479177387814f   // Y00 = 1/sqrt(4*pi)
#define PI_D      3.14159265358979323846

// output layout: concat of the 4 returned tensors, flattened, in order
#define OFF_LPC  0
#define OFF_POS  147456                          // 16*4*64*36
#define OFF_ANG  (OFF_POS + 66170880)            // + 16*64*64620
#define OFF_RAD  (OFF_ANG + 1033920)             // + 16*64620

// ---------------------------------------------------------------------------
// Device scratch (no allocations allowed)
// ---------------------------------------------------------------------------
__device__ float g_F[RB][KDIM];      // beta-dependent SH factor (incl. norm & sqrt2)
__device__ float g_ang[G_*C_*KDIM];  // angular coefficients
__device__ float g_rad[G_*R_];       // radial logits

__device__ __forceinline__ int lofk(int k) {
    const int t[36] = {0,1,1,1,2,2,2,2,2,3,3,3,3,3,3,3,
                       4,4,4,4,4,4,4,4,4,5,5,5,5,5,5,5,5,5,5,5};
    return t[k];
}

// ---------------------------------------------------------------------------
// K0: Gauss-Legendre nodes (n=180) + normalized associated Legendre -> g_F
// One thread per beta node. Recurrence coefficients precomputed into SMEM
// tables so the serial Newton chain carries no divides:
//   p2 = (ca[k]*x)*p1 - cb[k]*p0   (ca*x off-chain since x is fixed per iter)
// 4 float Newton iters (4 cyc/step chain) + 2 double polish (47 cyc/step).
// ---------------------------------------------------------------------------
__global__ void k_nodes() {
    __shared__ float  sca[RB + 1], scb[RB + 1];
    __shared__ double dca[RB + 1], dcb[RB + 1];

    int t = threadIdx.x;
    for (int k = t; k <= RB; k += blockDim.x) {
        if (k >= 2) {
            double a = (2.0 * k - 1.0) / (double)k;
            double c = (k - 1.0) / (double)k;
            dca[k] = a; dcb[k] = c;
            sca[k] = (float)a; scb[k] = (float)c;
        }
    }
    __syncthreads();

    int b = t;
    if (b >= RB) return;
    const int n = RB;
    int i = n - 1 - b;   // descending guess index -> ascending y (numpy order)

    float xf = (float)cos(PI_D * (i + 0.75) / (n + 0.5));

    // float Newton: coefficient-table recurrence, chain = 1 FFMA/step
    #pragma unroll 1
    for (int it = 0; it < 4; it++) {
        float p0 = 1.0f, p1 = xf;
        #pragma unroll 4
        for (int k = 2; k <= n; k++) {
            float p2 = fmaf(sca[k] * xf, p1, -scb[k] * p0);
            p0 = p1; p1 = p2;
        }
        float dp = n * (xf * p1 - p0) / (xf * xf - 1.0f);
        xf -= p1 / dp;
    }

    // double polish x2 (machine precision), divide-free chain
    double x = (double)xf;
    #pragma unroll 1
    for (int it = 0; it < 2; it++) {
        double p0 = 1.0, p1 = x;
        #pragma unroll 2
        for (int k = 2; k <= n; k++) {
            double p2 = fma(dca[k] * x, p1, -dcb[k] * p0);
            p0 = p1; p1 = p2;
        }
        double dp = n * (x * p1 - p0) / (x * x - 1.0);
        x -= p1 / dp;
    }

    // associated Legendre up to l=5 (Condon-Shortley), double precision
    double y = x;
    double somx2 = sqrt(fmax(1.0 - y * y, 0.0));
    double P[6][6];
    P[0][0] = 1.0;
    for (int m = 1; m <= 5; m++) P[m][m] = -(2.0 * m - 1.0) * somx2 * P[m-1][m-1];
    for (int m = 0; m < 5; m++)  P[m+1][m] = (2.0 * m + 1.0) * y * P[m][m];
    for (int m = 0; m <= 5; m++)
        for (int l = m + 2; l <= 5; l++)
            P[l][m] = ((2.0*l - 1.0) * y * P[l-1][m] - (l + m - 1.0) * P[l-2][m]) / (double)(l - m);

    double fact[11];
    fact[0] = 1.0;
    for (int q = 1; q <= 10; q++) fact[q] = fact[q-1] * q;

    for (int l = 0; l <= 5; l++) {
        for (int m = 0; m <= l; m++) {
            double N = sqrt((2.0*l + 1.0) / (4.0 * PI_D) * fact[l-m] / fact[l+m]);
            if (m == 0) {
                g_F[b][l*l + l] = (float)(N * P[l][0]);
            } else {
                double v = sqrt(2.0) * N * P[l][m];
                g_F[b][l*l + l + m] = (float)v;  // pairs with cos(m*alpha)
                g_F[b][l*l + l - m] = (float)v;  // pairs with sin(m*alpha)
            }
        }
    }
}

// ---------------------------------------------------------------------------
// K1: per-graph front section: gather focus node, species scaling, radial MLP,
// angular projections, log_position_coeffs + radial_logits outputs.
// One block per graph, 128 threads (= MUL).
// ---------------------------------------------------------------------------
__global__ void k_front(const float* __restrict__ emb,
                        const float* __restrict__ spec,
                        const float* __restrict__ Wr,
                        const float* __restrict__ Wm1,
                        const float* __restrict__ Wm2,
                        const float* __restrict__ Wa0, const float* __restrict__ Wa1,
                        const float* __restrict__ Wa2, const float* __restrict__ Wa3,
                        const float* __restrict__ Wa4, const float* __restrict__ Wa5,
                        const int* __restrict__ focus,
                        const int* __restrict__ tspec,
                        float* __restrict__ out) {
    __shared__ float s_sc[KDIM][MUL_ + 1];   // scaled irreps, padded vs bank conflicts
    __shared__ float s_r[64];
    __shared__ float s_h[128];
    __shared__ float s_rad[64];

    int g = blockIdx.x;
    int u = threadIdx.x;

    const float* f  = emb  + (size_t)focus[g] * EMB;
    const float* sp = spec + (size_t)tspec[g] * NIRR;

    #pragma unroll
    for (int l = 0; l <= 5; l++) {
        float s = sp[128*l + u];
        int d = 2*l + 1;
        const float* fb = f + 128*l*l + u*d;
        for (int m = 0; m < d; m++) s_sc[l*l + m][u] = fb[m] * s;
    }
    __syncthreads();

    // r = (scal0 @ W_radial) / sqrt(128)
    if (u < 64) {
        float acc = 0.f;
        #pragma unroll 8
        for (int v = 0; v < 128; v++) acc += s_sc[0][v] * Wr[v*64 + u];
        s_r[u] = acc * RSQRT_MUL;
    }
    __syncthreads();

    // h = softplus((r @ W_mlp1)/sqrt(64))
    {
        float acc = 0.f;
        #pragma unroll 8
        for (int j = 0; j < 64; j++) acc += s_r[j] * Wm1[j*128 + u];
        acc *= RSQRT_RAD;
        s_h[u] = fmaxf(acc, 0.f) + log1pf(expf(-fabsf(acc)));
    }
    __syncthreads();

    // radial_logits = (h @ W_mlp2)/sqrt(128)
    if (u < 64) {
        float acc = 0.f;
        #pragma unroll 8
        for (int v = 0; v < 128; v++) acc += s_h[v] * Wm2[v*64 + u];
        acc *= RSQRT_MUL;
        s_rad[u] = acc;
        g_rad[g*64 + u] = acc;
        out[OFF_RAD + g*64 + u] = acc;
    }
    __syncthreads();

    // angular coefficients ang[c][k] + log_position_coeffs
    const float* Wa[6] = {Wa0, Wa1, Wa2, Wa3, Wa4, Wa5};
    for (int o = u; o < C_*KDIM; o += 128) {
        int k = o >> 2, c = o & 3;
        int l = lofk(k);
        const float* w = Wa[l];
        float acc = 0.f;
        #pragma unroll 8
        for (int v = 0; v < 128; v++) acc += s_sc[k][v] * w[v*4 + c];
        acc *= RSQRT_MUL;
        g_ang[(g*C_ + c)*KDIM + k] = acc;

        float* lp = out + OFF_LPC + ((size_t)(g*C_ + c) * R_) * KDIM + k;
        if (k == 0) {
            #pragma unroll 8
            for (int r = 0; r < 64; r++) lp[r*KDIM] = acc + s_rad[r];
        } else {
            #pragma unroll 8
            for (int r = 0; r < 64; r++) lp[r*KDIM] = acc;
        }
    }
}

// ---------------------------------------------------------------------------
// K2 (fused): SH synthesis on the grid -> angular_logits, then broadcast-add
// radial*B0 -> position_logits. One thread per 4 consecutive pixels for one g;
// all heavy traffic is float4 (STG.128) write-only.
// grid = (ceil(NPIX4/256), G_), block = 256
// ---------------------------------------------------------------------------
__global__ void __launch_bounds__(256) k_grid(float* __restrict__ out) {
    __shared__ float s_ang[C_*KDIM];    // this g's angular coefficients
    __shared__ float s_radB[R_];        // radial logits * B0 for this g

    int g = blockIdx.y;

    if (threadIdx.x < C_*KDIM) s_ang[threadIdx.x] = g_ang[g*C_*KDIM + threadIdx.x];
    if (threadIdx.x >= 128 && threadIdx.x < 128 + R_)
        s_radB[threadIdx.x - 128] = g_rad[g*R_ + threadIdx.x - 128] * B0C;
    __syncthreads();

    int p = blockIdx.x * blockDim.x + threadIdx.x;   // 4-pixel group index
    if (p >= NPIX4) return;

    float lse4[4];

    #pragma unroll 1
    for (int s = 0; s < 4; s++) {
        int pix = 4*p + s;
        int b = pix / RA;
        int a = pix - b * RA;

        // alpha trig via Chebyshev recurrence
        float cosm[6], sinm[6];
        float al = (float)((2.0 * PI_D / (double)RA) * (double)a);
        __sincosf(al, &sinm[1], &cosm[1]);
        cosm[0] = 1.f; sinm[0] = 0.f;
        float c2 = 2.f * cosm[1];
        #pragma unroll
        for (int m = 2; m <= 5; m++) {
            cosm[m] = c2 * cosm[m-1] - cosm[m-2];
            sinm[m] = c2 * sinm[m-1] - sinm[m-2];
        }

        // load this beta row's F (9 x LDG.128, L1-resident)
        float F[KDIM];
        const float4* Fr = (const float4*)(&g_F[b][0]);
        #pragma unroll
        for (int q = 0; q < 9; q++) {
            float4 v = Fr[q];
            F[4*q] = v.x; F[4*q+1] = v.y; F[4*q+2] = v.z; F[4*q+3] = v.w;
        }

        float v0 = 0.f, v1 = 0.f, v2 = 0.f, v3 = 0.f;
        #pragma unroll
        for (int k = 0; k < KDIM; k++) {
            int l = lofk(k);
            int ms = k - l*l - l;
            float tg = (ms == 0) ? 1.f : ((ms > 0) ? cosm[ms] : sinm[-ms]);
            float bb = F[k] * tg;
            v0 = fmaf(s_ang[k],          bb, v0);
            v1 = fmaf(s_ang[KDIM + k],   bb, v1);
            v2 = fmaf(s_ang[2*KDIM + k], bb, v2);
            v3 = fmaf(s_ang[3*KDIM + k], bb, v3);
        }
        float mx = fmaxf(fmaxf(v0, v1), fmaxf(v2, v3));
        lse4[s] = mx + __logf(__expf(v0-mx) + __expf(v1-mx) + __expf(v2-mx) + __expf(v3-mx));
    }

    float4 L = make_float4(lse4[0], lse4[1], lse4[2], lse4[3]);

    // angular_logits (float4 store)
    *(float4*)(out + OFF_ANG + (size_t)g * NPIX + 4*p) = L;

    // position_logits[g, r, :] = lse + radial[g,r]*B0
    float* pp = out + OFF_POS + ((size_t)g * R_) * NPIX + 4*p;
    #pragma unroll 8
    for (int r = 0; r < R_; r++) {
        float rb = s_radB[r];
        float4 v = make_float4(L.x + rb, L.y + rb, L.z + rb, L.w + rb);
        *(float4*)pp = v;
        pp += NPIX;
    }
}

// ---------------------------------------------------------------------------
extern "C" void kernel_launch(void* const* d_in, const int* in_sizes, int n_in,
                              void* d_out, int out_size) {
    const float* emb  = (const float*)d_in[0];
    const float* spec = (const float*)d_in[1];
    const float* Wr   = (const float*)d_in[2];
    const float* Wm1  = (const float*)d_in[3];
    const float* Wm2  = (const float*)d_in[4];
    const float* Wa0  = (const float*)d_in[5];
    const float* Wa1  = (const float*)d_in[6];
    const float* Wa2  = (const float*)d_in[7];
    const float* Wa3  = (const float*)d_in[8];
    const float* Wa4  = (const float*)d_in[9];
    const float* Wa5  = (const float*)d_in[10];
    const int* focus  = (const int*)d_in[11];
    const int* tspec  = (const int*)d_in[12];
    float* out = (float*)d_out;

    k_nodes<<<1, 192>>>();
    k_front<<<G_, 128>>>(emb, spec, Wr, Wm1, Wm2,
                         Wa0, Wa1, Wa2, Wa3, Wa4, Wa5,
                         focus, tspec, out);
    dim3 gg((NPIX4 + 255) / 256, G_);
    k_grid<<<gg, 256>>>(out);
}

// round 3
// speedup vs baseline: 5.1151x; 1.4730x over previous
#include <cuda_runtime.h>
#include <cuda_bf16.h>
#include <math.h>

// ---------------------------------------------------------------------------
// Problem constants
// ---------------------------------------------------------------------------
#define G_      16
#define C_      4
#define R_      64
#define MUL_    128
#define KDIM    36          // (LMAX+1)^2
#define RB      180
#define RA      359
#define NPIX    (RB*RA)     // 64620
#define NPIX4   (NPIX/4)    // 16155
#define EMB     4608
#define NIRR    768
#define MDIM    12          // 11 signed-m slots (m=-5..5) + 1 pad

#define RSQRT_MUL 0.08838834764831845f   // 1/sqrt(128)
#define RSQRT_RAD 0.125f                 // 1/sqrt(64)
#define B0C       0.28209479177387814f   // Y00 = 1/sqrt(4*pi)
#define PI_D      3.14159265358979323846

// output layout: concat of the 4 returned tensors, flattened, in order
#define OFF_LPC  0
#define OFF_POS  147456                          // 16*4*64*36
#define OFF_ANG  (OFF_POS + 66170880)            // + 16*64*64620
#define OFF_RAD  (OFF_ANG + 1033920)             // + 16*64620

// ---------------------------------------------------------------------------
// Device scratch (no allocations allowed)
// ---------------------------------------------------------------------------
__device__ float g_F[RB][KDIM];              // beta SH factor (norm & sqrt2 included)
__device__ float g_ang[G_*C_*KDIM];          // angular coefficients
__device__ float g_rad[G_*R_];               // radial logits
__device__ float g_A[RB][G_][C_][MDIM];      // m-separated beta-collapsed coeffs

__device__ __forceinline__ int lofk(int k) {
    const int t[36] = {0,1,1,1,2,2,2,2,2,3,3,3,3,3,3,3,
                       4,4,4,4,4,4,4,4,4,5,5,5,5,5,5,5,5,5,5,5};
    return t[k];
}

// ---------------------------------------------------------------------------
// K0: Gauss-Legendre nodes (n=180) + normalized associated Legendre -> g_F
// One BLOCK per beta node (spreads the serial chains across SMs; avoids the
// single-SM FP64-throughput wall seen in R2). Float-only Newton: coefficient
// tables in smem, chain = 1 FFMA/step. Root error ~1e-7 -> F error ~1e-6,
// far inside the 1e-3 gate. Tiny l<=5 Legendre table kept in double (few ops).
// ---------------------------------------------------------------------------
__global__ void k_nodes() {
    __shared__ float sca[RB + 1], scb[RB + 1];

    const int n = RB;
    int lane = threadIdx.x;
    for (int k = 2 + lane; k <= n; k += 32) {
        sca[k] = (float)((2.0 * k - 1.0) / (double)k);
        scb[k] = (float)((k - 1.0) / (double)k);
    }
    __syncwarp();

    if (lane != 0) return;

    int b = blockIdx.x;
    int i = n - 1 - b;   // descending guess index -> ascending y (numpy order)

    float xf = (float)cos(PI_D * (i + 0.75) / (n + 0.5));

    #pragma unroll 1
    for (int it = 0; it < 6; it++) {
        float p0 = 1.0f, p1 = xf;
        #pragma unroll 4
        for (int k = 2; k <= n; k++) {
            float p2 = fmaf(sca[k] * xf, p1, -scb[k] * p0);
            p0 = p1; p1 = p2;
        }
        float dp = n * (xf * p1 - p0) / (xf * xf - 1.0f);
        xf -= p1 / dp;
    }

    // associated Legendre up to l=5 (Condon-Shortley); double (cheap, spread)
    double y = (double)xf;
    double somx2 = sqrt(fmax(1.0 - y * y, 0.0));
    double P[6][6];
    P[0][0] = 1.0;
    for (int m = 1; m <= 5; m++) P[m][m] = -(2.0 * m - 1.0) * somx2 * P[m-1][m-1];
    for (int m = 0; m < 5; m++)  P[m+1][m] = (2.0 * m + 1.0) * y * P[m][m];
    for (int m = 0; m <= 5; m++)
        for (int l = m + 2; l <= 5; l++)
            P[l][m] = ((2.0*l - 1.0) * y * P[l-1][m] - (l + m - 1.0) * P[l-2][m]) / (double)(l - m);

    double fact[11];
    fact[0] = 1.0;
    for (int q = 1; q <= 10; q++) fact[q] = fact[q-1] * q;

    for (int l = 0; l <= 5; l++) {
        for (int m = 0; m <= l; m++) {
            double N = sqrt((2.0*l + 1.0) / (4.0 * PI_D) * fact[l-m] / fact[l+m]);
            if (m == 0) {
                g_F[b][l*l + l] = (float)(N * P[l][0]);
            } else {
                double v = sqrt(2.0) * N * P[l][m];
                g_F[b][l*l + l + m] = (float)v;  // pairs with cos(m*alpha)
                g_F[b][l*l + l - m] = (float)v;  // pairs with sin(m*alpha)
            }
        }
    }
}

// ---------------------------------------------------------------------------
// K1: per-graph front section (gather, species scaling, radial MLP, angular
// projections, log_position_coeffs + radial_logits). One block per graph.
// ---------------------------------------------------------------------------
__global__ void k_front(const float* __restrict__ emb,
                        const float* __restrict__ spec,
                        const float* __restrict__ Wr,
                        const float* __restrict__ Wm1,
                        const float* __restrict__ Wm2,
                        const float* __restrict__ Wa0, const float* __restrict__ Wa1,
                        const float* __restrict__ Wa2, const float* __restrict__ Wa3,
                        const float* __restrict__ Wa4, const float* __restrict__ Wa5,
                        const int* __restrict__ focus,
                        const int* __restrict__ tspec,
                        float* __restrict__ out) {
    __shared__ float s_sc[KDIM][MUL_ + 1];
    __shared__ float s_r[64];
    __shared__ float s_h[128];
    __shared__ float s_rad[64];

    int g = blockIdx.x;
    int u = threadIdx.x;

    const float* f  = emb  + (size_t)focus[g] * EMB;
    const float* sp = spec + (size_t)tspec[g] * NIRR;

    #pragma unroll
    for (int l = 0; l <= 5; l++) {
        float s = sp[128*l + u];
        int d = 2*l + 1;
        const float* fb = f + 128*l*l + u*d;
        for (int m = 0; m < d; m++) s_sc[l*l + m][u] = fb[m] * s;
    }
    __syncthreads();

    if (u < 64) {
        float acc = 0.f;
        #pragma unroll 8
        for (int v = 0; v < 128; v++) acc += s_sc[0][v] * Wr[v*64 + u];
        s_r[u] = acc * RSQRT_MUL;
    }
    __syncthreads();

    {
        float acc = 0.f;
        #pragma unroll 8
        for (int j = 0; j < 64; j++) acc += s_r[j] * Wm1[j*128 + u];
        acc *= RSQRT_RAD;
        s_h[u] = fmaxf(acc, 0.f) + log1pf(expf(-fabsf(acc)));
    }
    __syncthreads();

    if (u < 64) {
        float acc = 0.f;
        #pragma unroll 8
        for (int v = 0; v < 128; v++) acc += s_h[v] * Wm2[v*64 + u];
        acc *= RSQRT_MUL;
        s_rad[u] = acc;
        g_rad[g*64 + u] = acc;
        out[OFF_RAD + g*64 + u] = acc;
    }
    __syncthreads();

    const float* Wa[6] = {Wa0, Wa1, Wa2, Wa3, Wa4, Wa5};
    for (int o = u; o < C_*KDIM; o += 128) {
        int k = o >> 2, c = o & 3;
        int l = lofk(k);
        const float* w = Wa[l];
        float acc = 0.f;
        #pragma unroll 8
        for (int v = 0; v < 128; v++) acc += s_sc[k][v] * w[v*4 + c];
        acc *= RSQRT_MUL;
        g_ang[(g*C_ + c)*KDIM + k] = acc;

        float* lp = out + OFF_LPC + ((size_t)(g*C_ + c) * R_) * KDIM + k;
        if (k == 0) {
            #pragma unroll 8
            for (int r = 0; r < 64; r++) lp[r*KDIM] = acc + s_rad[r];
        } else {
            #pragma unroll 8
            for (int r = 0; r < 64; r++) lp[r*KDIM] = acc;
        }
    }
}

// ---------------------------------------------------------------------------
// K1b: m-separation precompute. A[b][g][c][j] = sum_l ang[g,c,k(l,m)]*F[b,k(l,m)],
// j = m_signed + 5 (0..10), pad j=11 -> 0. One block per beta row.
// ---------------------------------------------------------------------------
__global__ void k_pre() {
    int b = blockIdx.x;
    __shared__ float sF[KDIM];
    if (threadIdx.x < KDIM) sF[threadIdx.x] = g_F[b][threadIdx.x];
    __syncthreads();

    for (int o = threadIdx.x; o < G_*C_*MDIM; o += blockDim.x) {
        int j  = o % MDIM;
        int gc = o / MDIM;           // g*4 + c
        float acc = 0.f;
        if (j < 11) {
            int ms = j - 5;
            int am = ms < 0 ? -ms : ms;
            for (int l = am; l <= 5; l++) {
                int k = l*l + l + ms;
                acc += g_ang[gc*KDIM + k] * sF[k];
            }
        }
        g_A[b][gc >> 2][gc & 3][j] = acc;
    }
}

// ---------------------------------------------------------------------------
// K2: grid synthesis via m-separated coefficients; write-only heavy traffic.
// Thread = 4 consecutive pixels, blockIdx.y = g-quarter (4 graphs each).
// Per (pixel,g,c): 11-FMA dot against trig vector t[m]. All stores float4.
// ---------------------------------------------------------------------------
__global__ void __launch_bounds__(256) k_grid(float* __restrict__ out) {
    __shared__ float s_radB[4][R_];

    int gq = blockIdx.y;             // 0..3, graphs 4*gq .. 4*gq+3
    if (threadIdx.x < 4*R_) {
        int gg = threadIdx.x >> 6, r = threadIdx.x & 63;
        s_radB[gg][r] = g_rad[(4*gq + gg)*R_ + r] * B0C;
    }
    __syncthreads();

    int p = blockIdx.x * blockDim.x + threadIdx.x;
    if (p >= NPIX4) return;

    // per-pixel trig vectors t[s][j]: j=5 -> 1, j>5 -> cos((j-5)a), j<5 -> sin((5-j)a)
    float t[4][MDIM];
    int bidx[4];
    #pragma unroll
    for (int s = 0; s < 4; s++) {
        int pix = 4*p + s;
        int b = pix / RA;
        int a = pix - b * RA;
        bidx[s] = b;

        float c1, s1;
        float al = (float)((2.0 * PI_D / (double)RA) * (double)a);
        __sincosf(al, &s1, &c1);
        float c2x = 2.f * c1;
        float cm2 = c2x*c1 - 1.f,  sm2 = c2x*s1;
        float cm3 = c2x*cm2 - c1,  sm3 = c2x*sm2 - s1;
        float cm4 = c2x*cm3 - cm2, sm4 = c2x*sm3 - sm2;
        float cm5 = c2x*cm4 - cm3, sm5 = c2x*sm4 - sm3;
        t[s][5] = 1.f;
        t[s][6] = c1;  t[s][4] = s1;
        t[s][7] = cm2; t[s][3] = sm2;
        t[s][8] = cm3; t[s][2] = sm3;
        t[s][9] = cm4; t[s][1] = sm4;
        t[s][10]= cm5; t[s][0] = sm5;
        t[s][11]= 0.f;
    }

    #pragma unroll 1
    for (int gg = 0; gg < 4; gg++) {
        int g = 4*gq + gg;
        float lse4[4];
        #pragma unroll
        for (int s = 0; s < 4; s++) {
            const float4* Ab = (const float4*)(&g_A[bidx[s]][g][0][0]);
            float v[4];
            #pragma unroll
            for (int c = 0; c < 4; c++) {
                float4 a0 = Ab[c*3 + 0];
                float4 a1 = Ab[c*3 + 1];
                float4 a2 = Ab[c*3 + 2];
                float acc;
                acc = a0.x * t[s][0];
                acc = fmaf(a0.y, t[s][1], acc);
                acc = fmaf(a0.z, t[s][2], acc);
                acc = fmaf(a0.w, t[s][3], acc);
                acc = fmaf(a1.x, t[s][4], acc);
                acc = fmaf(a1.y, t[s][5], acc);
                acc = fmaf(a1.z, t[s][6], acc);
                acc = fmaf(a1.w, t[s][7], acc);
                acc = fmaf(a2.x, t[s][8], acc);
                acc = fmaf(a2.y, t[s][9], acc);
                acc = fmaf(a2.z, t[s][10], acc);
                v[c] = acc;
            }
            float mx = fmaxf(fmaxf(v[0], v[1]), fmaxf(v[2], v[3]));
            lse4[s] = mx + __logf(__expf(v[0]-mx) + __expf(v[1]-mx)
                                + __expf(v[2]-mx) + __expf(v[3]-mx));
        }

        float4 L = make_float4(lse4[0], lse4[1], lse4[2], lse4[3]);
        *(float4*)(out + OFF_ANG + (size_t)g * NPIX + 4*p) = L;

        float* pp = out + OFF_POS + ((size_t)g * R_) * NPIX + 4*p;
        #pragma unroll 8
        for (int r = 0; r < R_; r++) {
            float rb = s_radB[gg][r];
            *(float4*)pp = make_float4(L.x + rb, L.y + rb, L.z + rb, L.w + rb);
            pp += NPIX;
        }
    }
}

// ---------------------------------------------------------------------------
extern "C" void kernel_launch(void* const* d_in, const int* in_sizes, int n_in,
                              void* d_out, int out_size) {
    const float* emb  = (const float*)d_in[0];
    const float* spec = (const float*)d_in[1];
    const float* Wr   = (const float*)d_in[2];
    const float* Wm1  = (const float*)d_in[3];
    const float* Wm2  = (const float*)d_in[4];
    const float* Wa0  = (const float*)d_in[5];
    const float* Wa1  = (const float*)d_in[6];
    const float* Wa2  = (const float*)d_in[7];
    const float* Wa3  = (const float*)d_in[8];
    const float* Wa4  = (const float*)d_in[9];
    const float* Wa5  = (const float*)d_in[10];
    const int* focus  = (const int*)d_in[11];
    const int* tspec  = (const int*)d_in[12];
    float* out = (float*)d_out;

    k_nodes<<<RB, 32>>>();
    k_front<<<G_, 128>>>(emb, spec, Wr, Wm1, Wm2,
                         Wa0, Wa1, Wa2, Wa3, Wa4, Wa5,
                         focus, tspec, out);
    k_pre<<<RB, 128>>>();
    dim3 gg((NPIX4 + 255) / 256, 4);
    k_grid<<<gg, 256>>>(out);
}

// round 4
// speedup vs baseline: 8.1122x; 1.5859x over previous
#include <cuda_runtime.h>
#include <cuda_bf16.h>
#include <math.h>

// ---------------------------------------------------------------------------
// Problem constants
// ---------------------------------------------------------------------------
#define G_      16
#define C_      4
#define R_      64
#define MUL_    128
#define KDIM    36          // (LMAX+1)^2
#define RB      180
#define RA      359
#define NPIX    (RB*RA)     // 64620
#define NPIX4   (NPIX/4)    // 16155
#define EMB     4608
#define NIRR    768
#define MDIM    12          // 11 signed-m slots (m=-5..5) + 1 pad

#define RSQRT_MUL 0.08838834764831845f   // 1/sqrt(128)
#define RSQRT_RAD 0.125f                 // 1/sqrt(64)
#define B0C       0.28209479177387814f   // Y00 = 1/sqrt(4*pi)
#define PI_D      3.14159265358979323846

// output layout: concat of the 4 returned tensors, flattened, in order
#define OFF_LPC  0
#define OFF_POS  147456                          // 16*4*64*36
#define OFF_ANG  (OFF_POS + 66170880)            // + 16*64*64620
#define OFF_RAD  (OFF_ANG + 1033920)             // + 16*64620

// ---------------------------------------------------------------------------
// Device scratch (no allocations allowed)
// ---------------------------------------------------------------------------
__device__ float g_F[RB][KDIM];      // beta SH factor (norm & sqrt2 included)
__device__ float g_ang[G_*C_*KDIM];  // angular coefficients
__device__ float g_rad[G_*R_];       // radial logits

__device__ __forceinline__ int lofk(int k) {
    const int t[36] = {0,1,1,1,2,2,2,2,2,3,3,3,3,3,3,3,
                       4,4,4,4,4,4,4,4,4,5,5,5,5,5,5,5,5,5,5,5};
    return t[k];
}

// ---------------------------------------------------------------------------
// K_setup: fused k_nodes (blocks 0..RB-1) + k_front (blocks RB..RB+G_-1).
// ---------------------------------------------------------------------------
__device__ void nodes_body(int b) {
    __shared__ float sca[RB + 1], scb[RB + 1];

    const int n = RB;
    for (int k = 2 + threadIdx.x; k <= n; k += 128) {
        sca[k] = (float)((2.0 * k - 1.0) / (double)k);
        scb[k] = (float)((k - 1.0) / (double)k);
    }
    __syncthreads();
    if (threadIdx.x != 0) return;

    int i = n - 1 - b;   // descending guess index -> ascending y (numpy order)
    float xf = (float)cos(PI_D * (i + 0.75) / (n + 0.5));

    // float Newton, divide-free coefficient-table recurrence
    #pragma unroll 1
    for (int it = 0; it < 4; it++) {
        float p0 = 1.0f, p1 = xf;
        #pragma unroll 4
        for (int k = 2; k <= n; k++) {
            float p2 = fmaf(sca[k] * xf, p1, -scb[k] * p0);
            p0 = p1; p1 = p2;
        }
        float dp = n * (xf * p1 - p0) / (xf * xf - 1.0f);
        xf -= p1 / dp;
    }

    // associated Legendre up to l=5 (Condon-Shortley); tiny double section
    double y = (double)xf;
    double somx2 = sqrt(fmax(1.0 - y * y, 0.0));
    double P[6][6];
    P[0][0] = 1.0;
    for (int m = 1; m <= 5; m++) P[m][m] = -(2.0 * m - 1.0) * somx2 * P[m-1][m-1];
    for (int m = 0; m < 5; m++)  P[m+1][m] = (2.0 * m + 1.0) * y * P[m][m];
    for (int m = 0; m <= 5; m++)
        for (int l = m + 2; l <= 5; l++)
            P[l][m] = ((2.0*l - 1.0) * y * P[l-1][m] - (l + m - 1.0) * P[l-2][m]) / (double)(l - m);

    double fact[11];
    fact[0] = 1.0;
    for (int q = 1; q <= 10; q++) fact[q] = fact[q-1] * q;

    for (int l = 0; l <= 5; l++) {
        for (int m = 0; m <= l; m++) {
            double N = sqrt((2.0*l + 1.0) / (4.0 * PI_D) * fact[l-m] / fact[l+m]);
            if (m == 0) {
                g_F[b][l*l + l] = (float)(N * P[l][0]);
            } else {
                double v = sqrt(2.0) * N * P[l][m];
                g_F[b][l*l + l + m] = (float)v;  // cos(m*alpha) partner
                g_F[b][l*l + l - m] = (float)v;  // sin(m*alpha) partner
            }
        }
    }
}

__device__ void front_body(int g,
                           const float* __restrict__ emb,
                           const float* __restrict__ spec,
                           const float* __restrict__ Wr,
                           const float* __restrict__ Wm1,
                           const float* __restrict__ Wm2,
                           const float* const* Wa,
                           const int* __restrict__ focus,
                           const int* __restrict__ tspec,
                           float* __restrict__ out) {
    __shared__ float s_sc[KDIM][MUL_ + 1];
    __shared__ float s_r[64];
    __shared__ float s_h[128];
    __shared__ float s_rad[64];

    int u = threadIdx.x;
    const float* f  = emb  + (size_t)focus[g] * EMB;
    const float* sp = spec + (size_t)tspec[g] * NIRR;

    #pragma unroll
    for (int l = 0; l <= 5; l++) {
        float s = sp[128*l + u];
        int d = 2*l + 1;
        const float* fb = f + 128*l*l + u*d;
        for (int m = 0; m < d; m++) s_sc[l*l + m][u] = fb[m] * s;
    }
    __syncthreads();

    if (u < 64) {
        float acc = 0.f;
        #pragma unroll 8
        for (int v = 0; v < 128; v++) acc += s_sc[0][v] * Wr[v*64 + u];
        s_r[u] = acc * RSQRT_MUL;
    }
    __syncthreads();

    {
        float acc = 0.f;
        #pragma unroll 8
        for (int j = 0; j < 64; j++) acc += s_r[j] * Wm1[j*128 + u];
        acc *= RSQRT_RAD;
        s_h[u] = fmaxf(acc, 0.f) + log1pf(expf(-fabsf(acc)));
    }
    __syncthreads();

    if (u < 64) {
        float acc = 0.f;
        #pragma unroll 8
        for (int v = 0; v < 128; v++) acc += s_h[v] * Wm2[v*64 + u];
        acc *= RSQRT_MUL;
        s_rad[u] = acc;
        g_rad[g*64 + u] = acc;
        out[OFF_RAD + g*64 + u] = acc;
    }
    __syncthreads();

    for (int o = u; o < C_*KDIM; o += 128) {
        int k = o >> 2, c = o & 3;
        int l = lofk(k);
        const float* w = Wa[l];
        float acc = 0.f;
        #pragma unroll 8
        for (int v = 0; v < 128; v++) acc += s_sc[k][v] * w[v*4 + c];
        acc *= RSQRT_MUL;
        g_ang[(g*C_ + c)*KDIM + k] = acc;

        float* lp = out + OFF_LPC + ((size_t)(g*C_ + c) * R_) * KDIM + k;
        if (k == 0) {
            #pragma unroll 8
            for (int r = 0; r < 64; r++) lp[r*KDIM] = acc + s_rad[r];
        } else {
            #pragma unroll 8
            for (int r = 0; r < 64; r++) lp[r*KDIM] = acc;
        }
    }
}

__global__ void __launch_bounds__(128) k_setup(
        const float* __restrict__ emb, const float* __restrict__ spec,
        const float* __restrict__ Wr, const float* __restrict__ Wm1,
        const float* __restrict__ Wm2,
        const float* __restrict__ Wa0, const float* __restrict__ Wa1,
        const float* __restrict__ Wa2, const float* __restrict__ Wa3,
        const float* __restrict__ Wa4, const float* __restrict__ Wa5,
        const int* __restrict__ focus, const int* __restrict__ tspec,
        float* __restrict__ out) {
    if (blockIdx.x < RB) {
        nodes_body(blockIdx.x);
    } else {
        const float* Wa[6] = {Wa0, Wa1, Wa2, Wa3, Wa4, Wa5};
        front_body(blockIdx.x - RB, emb, spec, Wr, Wm1, Wm2, Wa, focus, tspec, out);
    }
}

// ---------------------------------------------------------------------------
// K_grid: per-block inline m-separation (A table for its <=4 beta rows), then
// grid synthesis + LSE + radial broadcast. Write-only heavy traffic, all
// float4 streaming stores (__stcs). grid=(64, 16): blockIdx.y = graph.
// ---------------------------------------------------------------------------
__global__ void __launch_bounds__(256) k_grid(float* __restrict__ out) {
    __shared__ float s_A[4][C_][MDIM];    // m-separated coeffs for rows b0..b0+3
    __shared__ float s_radB[R_];

    int g  = blockIdx.y;
    int p0 = blockIdx.x * 256;            // first 4-pixel group of this block
    int b0 = (4 * p0) / RA;               // first beta row touched

    // radial * B0
    if (threadIdx.x < R_) s_radB[threadIdx.x] = g_rad[g*R_ + threadIdx.x] * B0C;

    // A[row][c][j] = sum_l g_ang[g,c,k(l,ms)] * g_F[b][k(l,ms)], j = ms+5
    if (threadIdx.x < 4 * C_ * MDIM) {
        int j   = threadIdx.x % MDIM;
        int c   = (threadIdx.x / MDIM) & 3;
        int row = threadIdx.x / (MDIM * C_);
        int b   = b0 + row;
        float acc = 0.f;
        if (j < 11 && b < RB) {
            int ms = j - 5;
            int am = ms < 0 ? -ms : ms;
            const float* ag = &g_ang[(g*C_ + c) * KDIM];
            #pragma unroll 1
            for (int l = am; l <= 5; l++) {
                int k = l*l + l + ms;
                acc += ag[k] * g_F[b][k];
            }
        }
        s_A[row][c][j] = acc;
    }
    __syncthreads();

    int p = p0 + threadIdx.x;
    if (p >= NPIX4) return;

    const float4* A4 = (const float4*)&s_A[0][0][0];

    float lse4[4];
    #pragma unroll
    for (int s = 0; s < 4; s++) {
        int pix = 4*p + s;
        int b = pix / RA;
        int a = pix - b * RA;
        int row = b - b0;

        // trig vector via Chebyshev recurrence
        float c1, s1;
        float al = (float)((2.0 * PI_D / (double)RA) * (double)a);
        __sincosf(al, &s1, &c1);
        float c2x = 2.f * c1;
        float cm2 = c2x*c1 - 1.f,  sm2 = c2x*s1;
        float cm3 = c2x*cm2 - c1,  sm3 = c2x*sm2 - s1;
        float cm4 = c2x*cm3 - cm2, sm4 = c2x*sm3 - sm2;
        float cm5 = c2x*cm4 - cm3, sm5 = c2x*sm4 - sm3;
        float t0 = sm5, t1 = sm4, t2 = sm3, t3 = sm2, t4 = s1;
        float t5 = 1.f, t6 = c1, t7 = cm2, t8 = cm3, t9 = cm4, t10 = cm5;

        float v[4];
        #pragma unroll
        for (int c = 0; c < 4; c++) {
            float4 a0 = A4[(row*4 + c)*3 + 0];
            float4 a1 = A4[(row*4 + c)*3 + 1];
            float4 a2 = A4[(row*4 + c)*3 + 2];
            float acc;
            acc = a0.x * t0;
            acc = fmaf(a0.y, t1, acc);
            acc = fmaf(a0.z, t2, acc);
            acc = fmaf(a0.w, t3, acc);
            acc = fmaf(a1.x, t4, acc);
            acc = fmaf(a1.y, t5, acc);
            acc = fmaf(a1.z, t6, acc);
            acc = fmaf(a1.w, t7, acc);
            acc = fmaf(a2.x, t8, acc);
            acc = fmaf(a2.y, t9, acc);
            acc = fmaf(a2.z, t10, acc);
            v[c] = acc;
        }
        float mx = fmaxf(fmaxf(v[0], v[1]), fmaxf(v[2], v[3]));
        lse4[s] = mx + __logf(__expf(v[0]-mx) + __expf(v[1]-mx)
                            + __expf(v[2]-mx) + __expf(v[3]-mx));
    }

    float4 L = make_float4(lse4[0], lse4[1], lse4[2], lse4[3]);
    __stcs((float4*)(out + OFF_ANG + (size_t)g * NPIX + 4*p), L);

    float* pp = out + OFF_POS + ((size_t)g * R_) * NPIX + 4*p;
    #pragma unroll 8
    for (int r = 0; r < R_; r++) {
        float rb = s_radB[r];
        __stcs((float4*)pp, make_float4(L.x + rb, L.y + rb, L.z + rb, L.w + rb));
        pp += NPIX;
    }
}

// ---------------------------------------------------------------------------
extern "C" void kernel_launch(void* const* d_in, const int* in_sizes, int n_in,
                              void* d_out, int out_size) {
    const float* emb  = (const float*)d_in[0];
    const float* spec = (const float*)d_in[1];
    const float* Wr   = (const float*)d_in[2];
    const float* Wm1  = (const float*)d_in[3];
    const float* Wm2  = (const float*)d_in[4];
    const float* Wa0  = (const float*)d_in[5];
    const float* Wa1  = (const float*)d_in[6];
    const float* Wa2  = (const float*)d_in[7];
    const float* Wa3  = (const float*)d_in[8];
    const float* Wa4  = (const float*)d_in[9];
    const float* Wa5  = (const float*)d_in[10];
    const int* focus  = (const int*)d_in[11];
    const int* tspec  = (const int*)d_in[12];
    float* out = (float*)d_out;

    k_setup<<<RB + G_, 128>>>(emb, spec, Wr, Wm1, Wm2,
                              Wa0, Wa1, Wa2, Wa3, Wa4, Wa5,
                              focus, tspec, out);
    dim3 gg((NPIX4 + 255) / 256, G_);
    k_grid<<<gg, 256>>>(out);
}